// round 12
// baseline (speedup 1.0000x reference)
#include <cuda_runtime.h>
#include <float.h>
#include <math.h>

// Problem constants
#define Bn   4
#define Qn   4
#define Fn   20
#define OBJn 20
#define Dn   4096
#define Mn   1000
#define ROWn (OBJn * Dn)          // 81920 floats per (frame|mem) row
#define BFn  (Bn * Fn)            // 80
#define KSPLIT 8
#define MPAD 2048
#define OUTBLKS 1184              // ~1 full wave of copy blocks

static const size_t RPN = (size_t)Qn * Bn * Fn * ROWn;   // 26,214,400 elems per big output

// ---------------- device scratch ----------------
__device__ float g_mem_mp[2 * Mn * Dn];          // 32.8 MB: normalized maxpooled mem rows
__device__ float g_rmaxn[BFn * Dn];              // normalized maxpooled R rows
__device__ float g_invnorm[BFn * OBJn];          // per-region inverse norms
__device__ float g_partial[KSPLIT * BFn * MPAD]; // k-split partial dots
__device__ int   g_sim[2 * BFn];                 // sim1 (0..79), sim2 (80..159)
__device__ int   g_high[16], g_low[16];          // indexed by b*4+q

// ---------------- helpers ----------------
__device__ __forceinline__ float block_reduce_sum(float v) {
    __shared__ float sh[32];
    __shared__ float res;
    int lane = threadIdx.x & 31, w = threadIdx.x >> 5;
#pragma unroll
    for (int o = 16; o; o >>= 1) v += __shfl_down_sync(0xffffffffu, v, o);
    __syncthreads();
    if (!lane) sh[w] = v;
    __syncthreads();
    if (w == 0) {
        float x = (lane < (int)(blockDim.x >> 5)) ? sh[lane] : 0.f;
#pragma unroll
        for (int o = 16; o; o >>= 1) x += __shfl_down_sync(0xffffffffu, x, o);
        if (!lane) res = x;
    }
    __syncthreads();
    return res;
}

__device__ __forceinline__ float4 fmax4(float4 a, float4 b) {
    a.x = fmaxf(a.x, b.x); a.y = fmaxf(a.y, b.y);
    a.z = fmaxf(a.z, b.z); a.w = fmaxf(a.w, b.w);
    return a;
}

// ---------------- K_sel: frame selection from qr/rnd only ----------------
__global__ void k_sel(const float* __restrict__ qr, const int* __restrict__ rnd) {
    int t = threadIdx.x;
    if (t >= 16) return;
    int b = t >> 2, q = t & 3;                // t = b*4 + q
    const float* w = qr + (b * Qn + q) * Fn;
    int hi = 0; float hv = w[0];
    for (int f = 1; f < Fn; f++) if (w[f] > hv) { hv = w[f]; hi = f; }
    int rr = rnd[b * Qn + q];
    int lo = 0;
    for (int i = 0; i < Fn; i++) {
        int rank = 0;
        for (int j = 0; j < Fn; j++)
            rank += (w[j] < w[i]) || (w[j] == w[i] && j < i);
        if (rank == rr) { lo = i; break; }
    }
    g_high[t] = hi; g_low[t] = lo;
}

// ---------------- K_rstats: per-(b,f) region norms + maxpool + l2norm ----------------
__global__ __launch_bounds__(256) void k_rstats(const float* __restrict__ inp) {
    int bf = blockIdx.x;
    const float* base = inp + (size_t)bf * ROWn;
    float4 mx[4];
#pragma unroll
    for (int i = 0; i < 4; i++) mx[i] = make_float4(-FLT_MAX, -FLT_MAX, -FLT_MAX, -FLT_MAX);
    for (int o = 0; o < OBJn; o++) {
        float4 x[4];
        const float4* p = (const float4*)(base + (size_t)o * Dn);
        float s = 0.f;
#pragma unroll
        for (int i = 0; i < 4; i++) {
            x[i] = p[threadIdx.x + i * 256];
            s += x[i].x * x[i].x + x[i].y * x[i].y + x[i].z * x[i].z + x[i].w * x[i].w;
        }
        s = block_reduce_sum(s);
        float inv = 1.f / fmaxf(sqrtf(s), 1e-12f);
        if (threadIdx.x == 0) g_invnorm[bf * OBJn + o] = inv;
#pragma unroll
        for (int i = 0; i < 4; i++) {
            float4 v = x[i];
            v.x *= inv; v.y *= inv; v.z *= inv; v.w *= inv;
            mx[i] = fmax4(mx[i], v);
        }
    }
    float s2 = 0.f;
#pragma unroll
    for (int i = 0; i < 4; i++)
        s2 += mx[i].x * mx[i].x + mx[i].y * mx[i].y + mx[i].z * mx[i].z + mx[i].w * mx[i].w;
    s2 = block_reduce_sum(s2);
    float inv2 = 1.f / fmaxf(sqrtf(s2), 1e-12f);
    float4* out = (float4*)(g_rmaxn + (size_t)bf * Dn);
#pragma unroll
    for (int i = 0; i < 4; i++) {
        float4 v = mx[i];
        v.x *= inv2; v.y *= inv2; v.z *= inv2; v.w *= inv2;
        out[threadIdx.x + i * 256] = v;
    }
}

// ---------------- K_mem_mp: mem max-pool + l2norm (proven 100us @ 86% DRAM) ----------
__global__ __launch_bounds__(256) void k_mem_mp(const float* __restrict__ mem1,
                                                const float* __restrict__ mem2) {
    int row = blockIdx.x;
    const float* src = (row >= Mn) ? (mem2 + (size_t)(row - Mn) * ROWn)
                                   : (mem1 + (size_t)row * ROWn);
    float4 mx[4];
#pragma unroll
    for (int i = 0; i < 4; i++) mx[i] = make_float4(-FLT_MAX, -FLT_MAX, -FLT_MAX, -FLT_MAX);
    for (int o = 0; o < OBJn; o++) {
        const float4* p = (const float4*)(src + (size_t)o * Dn);
#pragma unroll
        for (int i = 0; i < 4; i++) mx[i] = fmax4(mx[i], p[threadIdx.x + i * 256]);
    }
    float s = 0.f;
#pragma unroll
    for (int i = 0; i < 4; i++)
        s += mx[i].x * mx[i].x + mx[i].y * mx[i].y + mx[i].z * mx[i].z + mx[i].w * mx[i].w;
    s = block_reduce_sum(s);
    float inv = 1.f / fmaxf(sqrtf(s), 1e-12f);
    float4* out = (float4*)(g_mem_mp + (size_t)row * Dn);
#pragma unroll
    for (int i = 0; i < 4; i++) {
        float4 v = mx[i];
        v.x *= inv; v.y *= inv; v.z *= inv; v.w *= inv;
        out[threadIdx.x + i * 256] = v;
    }
}

// ---------------- K_gemm: proven 35us FMA-floor kernel ----------------
__global__ __launch_bounds__(256) void k_gemm() {
    __shared__ float As[80][33];
    __shared__ float Bs[64][33];
    int tid = threadIdx.x;
    int tx = tid & 15, ty = tid >> 4;     // tx: m (16x4=64), ty: r (16x5=80)
    int m0 = blockIdx.x * 64;
    int kbase = blockIdx.y * 512;
    float acc[5][4];
#pragma unroll
    for (int i = 0; i < 5; i++)
#pragma unroll
        for (int j = 0; j < 4; j++) acc[i][j] = 0.f;

    for (int kc = 0; kc < 16; kc++) {
        int k0 = kbase + kc * 32;
        __syncthreads();
#pragma unroll
        for (int idx = tid; idx < 80 * 32; idx += 256) {
            int r = idx >> 5, kk = idx & 31;
            As[r][kk] = g_rmaxn[(size_t)r * Dn + k0 + kk];
        }
#pragma unroll
        for (int idx = tid; idx < 64 * 32; idx += 256) {
            int m = idx >> 5, kk = idx & 31;
            int mg = m0 + m;
            Bs[m][kk] = (mg < 2 * Mn) ? g_mem_mp[(size_t)mg * Dn + k0 + kk] : 0.f;
        }
        __syncthreads();
#pragma unroll
        for (int kk = 0; kk < 32; kk++) {
            float a[5], b[4];
#pragma unroll
            for (int i = 0; i < 5; i++) a[i] = As[ty * 5 + i][kk];
#pragma unroll
            for (int j = 0; j < 4; j++) b[j] = Bs[tx * 4 + j][kk];
#pragma unroll
            for (int i = 0; i < 5; i++)
#pragma unroll
                for (int j = 0; j < 4; j++) acc[i][j] = fmaf(a[i], b[j], acc[i][j]);
        }
    }
    float* dst = g_partial + (size_t)blockIdx.y * BFn * MPAD;
#pragma unroll
    for (int i = 0; i < 5; i++)
#pragma unroll
        for (int j = 0; j < 4; j++)
            dst[(ty * 5 + i) * MPAD + m0 + tx * 4 + j] = acc[i][j];
}

// ---------------- K_argmax: one block per (row, mem-half) — proven ~4us --------------
__global__ __launch_bounds__(512) void k_argmax() {
    int r = blockIdx.x >> 1;
    int h = blockIdx.x & 1;
    int tid = threadIdx.x;
    float bv = -FLT_MAX;
    int   bm = 0;
    for (int m = tid; m < Mn; m += 512) {
        int mg = h * Mn + m;
        float s = 0.f;
#pragma unroll
        for (int ks = 0; ks < KSPLIT; ks++)
            s += g_partial[(size_t)ks * BFn * MPAD + (size_t)r * MPAD + mg];
        if (s > bv || (s == bv && m < bm)) { bv = s; bm = m; }
    }
    __shared__ float sv[512];
    __shared__ int   sm2[512];
    sv[tid] = bv; sm2[tid] = bm;
    __syncthreads();
    for (int st = 256; st; st >>= 1) {
        if (tid < st) {
            float ov = sv[tid + st]; int om = sm2[tid + st];
            if (ov > sv[tid] || (ov == sv[tid] && om < sm2[tid])) {
                sv[tid] = ov; sm2[tid] = om;
            }
        }
        __syncthreads();
    }
    if (tid == 0) g_sim[h * BFn + r] = sm2[0];
}

// ---------------- K_out: ALL output writes, one grid-stride kernel (R10: 41us) -------
// Flat item list: [0,6400): fill chunks  [6400,6912): replace chunks  6912: sims.
#define FILL_ITEMS (BFn * 80)                 // 6400
#define REPL_ITEMS (32 * 16)                  // 512 (32 rows x 16 chunks)
#define NITEMS     (FILL_ITEMS + REPL_ITEMS + 1)

__global__ __launch_bounds__(256) void k_out(const float* __restrict__ inp,
                                             const float* __restrict__ mem1,
                                             const float* __restrict__ mem2,
                                             float* __restrict__ out,
                                             long long out_size) {
    int tid = threadIdx.x;
    float4* o4 = (float4*)out;
    const size_t rpn4 = RPN / 4;
    for (int it = blockIdx.x; it < NITEMS; it += gridDim.x) {
        if (it < FILL_ITEMS) {
            // ---- fill: normalize + fan-out to Rp/Rn copies ----
            int bf = it / 80;
            int ch = it % 80;
            int b = bf / Fn, f = bf % Fn;
            int e4 = ch * 256 + tid;           // 0..20479 within the row
            int oo = e4 >> 10;                 // region (1024 float4 per region)
            float inv = g_invnorm[bf * OBJn + oo];
            float4 v = ((const float4*)(inp + (size_t)bf * ROWn))[e4];
            v.x *= inv; v.y *= inv; v.z *= inv; v.w *= inv;
#pragma unroll
            for (int q = 0; q < 4; q++) {
                int lo = g_low[b * 4 + q], hi = g_high[b * 4 + q];
                size_t ob = ((size_t)((q * Bn + b) * Fn + f)) * (ROWn / 4) + e4;
                if (f != lo) o4[ob] = v;            // Rp copy
                if (f != hi) o4[rpn4 + ob] = v;     // Rn copy
            }
        } else if (it < FILL_ITEMS + REPL_ITEMS) {
            // ---- replace: gather mem rows ----
            int ri = it - FILL_ITEMS;
            int t2 = ri / 16;                  // (bq, which)
            int ch = ri % 16;
            int which = t2 & 1;                // 0: Rp/low/mem1  1: Rn/high/mem2
            int bq = t2 >> 1;
            int b = bq >> 2, q = bq & 3;
            int lo = g_low[bq];
            int f, row;
            const float* src;
            if (which == 0) { f = lo;         row = g_sim[b * Fn + lo];       src = mem1; }
            else            { f = g_high[bq]; row = g_sim[BFn + b * Fn + lo]; src = mem2; }
            const float4* s4 = (const float4*)(src + (size_t)row * ROWn);
            float4* d4 = (float4*)(out + (size_t)which * RPN +
                                   ((size_t)((q * Bn + b) * Fn + f)) * ROWn);
            int base = ch * 1280;
#pragma unroll
            for (int i = 0; i < 5; i++) {
                int e4 = base + tid + i * 256;
                d4[e4] = s4[e4];
            }
        } else {
            // ---- sims ----
            if (tid < 16) {
                int bq = tid;
                int b = bq >> 2, q = bq & 3;
                long long rpn2 = (long long)(2 * RPN);
                if (out_size >= rpn2 + 32) {
                    out[(size_t)rpn2 + (q * Bn + b)]      =
                        (float)g_sim[BFn + b * Fn + g_high[bq]];   // high_sim
                    out[(size_t)rpn2 + 16 + (q * Bn + b)] =
                        (float)g_sim[b * Fn + g_low[bq]];          // low_sim
                }
            }
        }
    }
}

// ---------------- launch: strictly serial, single stream, deterministic --------------
extern "C" void kernel_launch(void* const* d_in, const int* in_sizes, int n_in,
                              void* d_out, int out_size) {
    const float* qr   = (const float*)d_in[0];   // [4,4,20]
    const float* inp  = (const float*)d_in[1];   // [4,20,20,4096]
    const float* mem1 = (const float*)d_in[2];   // [1000,81920]
    const float* mem2 = (const float*)d_in[3];   // [1000,81920]
    const int*   rnd  = (const int*)d_in[4];     // [4,4,1]
    float* out = (float*)d_out;

    k_sel<<<1, 32>>>(qr, rnd);                   // ~1us
    k_rstats<<<BFn, 256>>>(inp);                 // ~6us  (26 MB, before the big stream)
    k_mem_mp<<<2 * Mn, 256>>>(mem1, mem2);       // ~100us (655 MB @ DRAM floor, alone)
    k_gemm<<<dim3(32, KSPLIT), 256>>>();         // ~35us  (FMA floor, B in L2)
    k_argmax<<<2 * BFn, 512>>>();                // ~4us
    k_out<<<OUTBLKS, 256>>>(inp, mem1, mem2, out, (long long)out_size);  // ~41us
}

// round 13
// speedup vs baseline: 1.1031x; 1.1031x over previous
#include <cuda_runtime.h>
#include <float.h>
#include <math.h>

// Problem constants
#define Bn   4
#define Qn   4
#define Fn   20
#define OBJn 20
#define Dn   4096
#define Mn   1000
#define ROWn (OBJn * Dn)          // 81920 floats per (frame|mem) row
#define BFn  (Bn * Fn)            // 80
#define KSPLIT 16
#define KPER   (Dn / KSPLIT)      // 256 k per block
#define MPAD 2048
#define OUTBLKS 1184

static const size_t RPN = (size_t)Qn * Bn * Fn * ROWn;   // 26,214,400 elems per big output

// ---------------- device scratch ----------------
__device__ float g_mem_mp[2 * Mn * Dn];          // 32.8 MB: normalized maxpooled mem rows
__device__ float g_rmaxn[BFn * Dn];              // normalized maxpooled R rows
__device__ float g_invnorm[BFn * OBJn];          // per-region inverse norms
__device__ float g_partial[KSPLIT * BFn * MPAD]; // 10.5 MB k-split partial dots
__device__ int   g_sim[2 * BFn];                 // sim1 (0..79), sim2 (80..159)
__device__ int   g_high[16], g_low[16];          // indexed by b*4+q

// ---------------- helpers ----------------
__device__ __forceinline__ float block_reduce_sum(float v) {
    __shared__ float sh[32];
    __shared__ float res;
    int lane = threadIdx.x & 31, w = threadIdx.x >> 5;
#pragma unroll
    for (int o = 16; o; o >>= 1) v += __shfl_down_sync(0xffffffffu, v, o);
    __syncthreads();
    if (!lane) sh[w] = v;
    __syncthreads();
    if (w == 0) {
        float x = (lane < (int)(blockDim.x >> 5)) ? sh[lane] : 0.f;
#pragma unroll
        for (int o = 16; o; o >>= 1) x += __shfl_down_sync(0xffffffffu, x, o);
        if (!lane) res = x;
    }
    __syncthreads();
    return res;
}

__device__ __forceinline__ float4 fmax4(float4 a, float4 b) {
    a.x = fmaxf(a.x, b.x); a.y = fmaxf(a.y, b.y);
    a.z = fmaxf(a.z, b.z); a.w = fmaxf(a.w, b.w);
    return a;
}

// ---------------- K_sel ----------------
__global__ void k_sel(const float* __restrict__ qr, const int* __restrict__ rnd) {
    int t = threadIdx.x;
    if (t >= 16) return;
    int b = t >> 2, q = t & 3;                // t = b*4 + q
    const float* w = qr + (b * Qn + q) * Fn;
    int hi = 0; float hv = w[0];
    for (int f = 1; f < Fn; f++) if (w[f] > hv) { hv = w[f]; hi = f; }
    int rr = rnd[b * Qn + q];
    int lo = 0;
    for (int i = 0; i < Fn; i++) {
        int rank = 0;
        for (int j = 0; j < Fn; j++)
            rank += (w[j] < w[i]) || (w[j] == w[i] && j < i);
        if (rank == rr) { lo = i; break; }
    }
    g_high[t] = hi; g_low[t] = lo;
}

// ---------------- K_rstats ----------------
__global__ __launch_bounds__(256) void k_rstats(const float* __restrict__ inp) {
    int bf = blockIdx.x;
    const float* base = inp + (size_t)bf * ROWn;
    float4 mx[4];
#pragma unroll
    for (int i = 0; i < 4; i++) mx[i] = make_float4(-FLT_MAX, -FLT_MAX, -FLT_MAX, -FLT_MAX);
    for (int o = 0; o < OBJn; o++) {
        float4 x[4];
        const float4* p = (const float4*)(base + (size_t)o * Dn);
        float s = 0.f;
#pragma unroll
        for (int i = 0; i < 4; i++) {
            x[i] = p[threadIdx.x + i * 256];
            s += x[i].x * x[i].x + x[i].y * x[i].y + x[i].z * x[i].z + x[i].w * x[i].w;
        }
        s = block_reduce_sum(s);
        float inv = 1.f / fmaxf(sqrtf(s), 1e-12f);
        if (threadIdx.x == 0) g_invnorm[bf * OBJn + o] = inv;
#pragma unroll
        for (int i = 0; i < 4; i++) {
            float4 v = x[i];
            v.x *= inv; v.y *= inv; v.z *= inv; v.w *= inv;
            mx[i] = fmax4(mx[i], v);
        }
    }
    float s2 = 0.f;
#pragma unroll
    for (int i = 0; i < 4; i++)
        s2 += mx[i].x * mx[i].x + mx[i].y * mx[i].y + mx[i].z * mx[i].z + mx[i].w * mx[i].w;
    s2 = block_reduce_sum(s2);
    float inv2 = 1.f / fmaxf(sqrtf(s2), 1e-12f);
    float4* out = (float4*)(g_rmaxn + (size_t)bf * Dn);
#pragma unroll
    for (int i = 0; i < 4; i++) {
        float4 v = mx[i];
        v.x *= inv2; v.y *= inv2; v.z *= inv2; v.w *= inv2;
        out[threadIdx.x + i * 256] = v;
    }
}

// ---------------- K_mem_mp (proven at DRAM floor) ----------------
__global__ __launch_bounds__(256) void k_mem_mp(const float* __restrict__ mem1,
                                                const float* __restrict__ mem2) {
    int row = blockIdx.x;
    const float* src = (row >= Mn) ? (mem2 + (size_t)(row - Mn) * ROWn)
                                   : (mem1 + (size_t)row * ROWn);
    float4 mx[4];
#pragma unroll
    for (int i = 0; i < 4; i++) mx[i] = make_float4(-FLT_MAX, -FLT_MAX, -FLT_MAX, -FLT_MAX);
    for (int o = 0; o < OBJn; o++) {
        const float4* p = (const float4*)(src + (size_t)o * Dn);
#pragma unroll
        for (int i = 0; i < 4; i++) mx[i] = fmax4(mx[i], p[threadIdx.x + i * 256]);
    }
    float s = 0.f;
#pragma unroll
    for (int i = 0; i < 4; i++)
        s += mx[i].x * mx[i].x + mx[i].y * mx[i].y + mx[i].z * mx[i].z + mx[i].w * mx[i].w;
    s = block_reduce_sum(s);
    float inv = 1.f / fmaxf(sqrtf(s), 1e-12f);
    float4* out = (float4*)(g_mem_mp + (size_t)row * Dn);
#pragma unroll
    for (int i = 0; i < 4; i++) {
        float4 v = mx[i];
        v.x *= inv; v.y *= inv; v.z *= inv; v.w *= inv;
        out[threadIdx.x + i * 256] = v;
    }
}

// ---------------- K_gemm v2: transposed tiles, 5x8 micro, vector LDS -----------------
// grid (16 m-tiles of 128, KSPLIT k-splits of 256), 256 threads.
// Per kk: 3 LDS.128 + 1 LDS.32 + 1 LDS.128-pair for A/B (5 ld-instr) + 40 FMA.
__global__ __launch_bounds__(256) void k_gemm() {
    __shared__ float As[32][81];    // [kk][r]  (81: A-store banks (c4*4+j)*17+r all distinct)
    __shared__ float Bs[32][129];   // [kk][m]  (129: B-store banks (c4*4+j)+m all distinct)
    int tid = threadIdx.x;
    int tx = tid & 15;              // m group: 8 each -> 128
    int ty = tid >> 4;              // r group: 5 each -> 80
    int m0 = blockIdx.x * 128;
    int kbase = blockIdx.y * KPER;

    float acc[5][8];
#pragma unroll
    for (int i = 0; i < 5; i++)
#pragma unroll
        for (int j = 0; j < 8; j++) acc[i][j] = 0.f;

    for (int kc = 0; kc < KPER / 32; kc++) {
        int k0 = kbase + kc * 32;
        __syncthreads();
        // A tile: 80 r x 32 k, transposed store (coalesced float4 gmem reads)
        for (int idx = tid; idx < 640; idx += 256) {
            int r = idx >> 3, c4 = idx & 7;
            float4 v = *(const float4*)(g_rmaxn + (size_t)r * Dn + k0 + c4 * 4);
            As[c4 * 4 + 0][r] = v.x; As[c4 * 4 + 1][r] = v.y;
            As[c4 * 4 + 2][r] = v.z; As[c4 * 4 + 3][r] = v.w;
        }
        // B tile: 128 m x 32 k, transposed store
#pragma unroll
        for (int l = 0; l < 4; l++) {
            int idx = tid + l * 256;
            int m = idx >> 3, c4 = idx & 7;
            int mg = m0 + m;
            float4 v = make_float4(0.f, 0.f, 0.f, 0.f);
            if (mg < 2 * Mn)
                v = *(const float4*)(g_mem_mp + (size_t)mg * Dn + k0 + c4 * 4);
            Bs[c4 * 4 + 0][m] = v.x; Bs[c4 * 4 + 1][m] = v.y;
            Bs[c4 * 4 + 2][m] = v.z; Bs[c4 * 4 + 3][m] = v.w;
        }
        __syncthreads();
#pragma unroll
        for (int kk = 0; kk < 32; kk++) {
            float a[5], b[8];
#pragma unroll
            for (int i = 0; i < 5; i++) a[i] = As[kk][ty * 5 + i];
#pragma unroll
            for (int j = 0; j < 8; j++) b[j] = Bs[kk][tx * 8 + j];
#pragma unroll
            for (int i = 0; i < 5; i++)
#pragma unroll
                for (int j = 0; j < 8; j++) acc[i][j] = fmaf(a[i], b[j], acc[i][j]);
        }
    }
    // vectorized partial store
    float* dst = g_partial + (size_t)blockIdx.y * BFn * MPAD;
#pragma unroll
    for (int i = 0; i < 5; i++) {
        float4* p = (float4*)(dst + (ty * 5 + i) * MPAD + m0 + tx * 8);
        p[0] = make_float4(acc[i][0], acc[i][1], acc[i][2], acc[i][3]);
        p[1] = make_float4(acc[i][4], acc[i][5], acc[i][6], acc[i][7]);
    }
}

// ---------------- K_argmax: one block per (row, mem-half) ----------------
__global__ __launch_bounds__(512) void k_argmax() {
    int r = blockIdx.x >> 1;
    int h = blockIdx.x & 1;
    int tid = threadIdx.x;
    float bv = -FLT_MAX;
    int   bm = 0;
    for (int m = tid; m < Mn; m += 512) {
        int mg = h * Mn + m;
        float s = 0.f;
#pragma unroll
        for (int ks = 0; ks < KSPLIT; ks++)
            s += g_partial[(size_t)ks * BFn * MPAD + (size_t)r * MPAD + mg];
        if (s > bv || (s == bv && m < bm)) { bv = s; bm = m; }
    }
    __shared__ float sv[512];
    __shared__ int   sm2[512];
    sv[tid] = bv; sm2[tid] = bm;
    __syncthreads();
    for (int st = 256; st; st >>= 1) {
        if (tid < st) {
            float ov = sv[tid + st]; int om = sm2[tid + st];
            if (ov > sv[tid] || (ov == sv[tid] && om < sm2[tid])) {
                sv[tid] = ov; sm2[tid] = om;
            }
        }
        __syncthreads();
    }
    if (tid == 0) g_sim[h * BFn + r] = sm2[0];
}

// ---------------- K_out: all output writes (R10-proven 41us) ----------------
#define FILL_ITEMS (BFn * 80)                 // 6400
#define REPL_ITEMS (32 * 16)                  // 512
#define NITEMS     (FILL_ITEMS + REPL_ITEMS + 1)

__global__ __launch_bounds__(256) void k_out(const float* __restrict__ inp,
                                             const float* __restrict__ mem1,
                                             const float* __restrict__ mem2,
                                             float* __restrict__ out,
                                             long long out_size) {
    int tid = threadIdx.x;
    float4* o4 = (float4*)out;
    const size_t rpn4 = RPN / 4;
    for (int it = blockIdx.x; it < NITEMS; it += gridDim.x) {
        if (it < FILL_ITEMS) {
            int bf = it / 80;
            int ch = it % 80;
            int b = bf / Fn, f = bf % Fn;
            int e4 = ch * 256 + tid;
            int oo = e4 >> 10;
            float inv = g_invnorm[bf * OBJn + oo];
            float4 v = ((const float4*)(inp + (size_t)bf * ROWn))[e4];
            v.x *= inv; v.y *= inv; v.z *= inv; v.w *= inv;
#pragma unroll
            for (int q = 0; q < 4; q++) {
                int lo = g_low[b * 4 + q], hi = g_high[b * 4 + q];
                size_t ob = ((size_t)((q * Bn + b) * Fn + f)) * (ROWn / 4) + e4;
                if (f != lo) o4[ob] = v;            // Rp copy
                if (f != hi) o4[rpn4 + ob] = v;     // Rn copy
            }
        } else if (it < FILL_ITEMS + REPL_ITEMS) {
            int ri = it - FILL_ITEMS;
            int t2 = ri / 16;
            int ch = ri % 16;
            int which = t2 & 1;                // 0: Rp/low/mem1  1: Rn/high/mem2
            int bq = t2 >> 1;
            int b = bq >> 2, q = bq & 3;
            int lo = g_low[bq];
            int f, row;
            const float* src;
            if (which == 0) { f = lo;         row = g_sim[b * Fn + lo];       src = mem1; }
            else            { f = g_high[bq]; row = g_sim[BFn + b * Fn + lo]; src = mem2; }
            const float4* s4 = (const float4*)(src + (size_t)row * ROWn);
            float4* d4 = (float4*)(out + (size_t)which * RPN +
                                   ((size_t)((q * Bn + b) * Fn + f)) * ROWn);
            int base = ch * 1280;
#pragma unroll
            for (int i = 0; i < 5; i++) {
                int e4 = base + tid + i * 256;
                d4[e4] = s4[e4];
            }
        } else {
            if (tid < 16) {
                int bq = tid;
                int b = bq >> 2, q = bq & 3;
                long long rpn2 = (long long)(2 * RPN);
                if (out_size >= rpn2 + 32) {
                    out[(size_t)rpn2 + (q * Bn + b)]      =
                        (float)g_sim[BFn + b * Fn + g_high[bq]];   // high_sim
                    out[(size_t)rpn2 + 16 + (q * Bn + b)] =
                        (float)g_sim[b * Fn + g_low[bq]];          // low_sim
                }
            }
        }
    }
}

// ---------------- launch: strictly serial, deterministic ----------------
extern "C" void kernel_launch(void* const* d_in, const int* in_sizes, int n_in,
                              void* d_out, int out_size) {
    const float* qr   = (const float*)d_in[0];   // [4,4,20]
    const float* inp  = (const float*)d_in[1];   // [4,20,20,4096]
    const float* mem1 = (const float*)d_in[2];   // [1000,81920]
    const float* mem2 = (const float*)d_in[3];   // [1000,81920]
    const int*   rnd  = (const int*)d_in[4];     // [4,4,1]
    float* out = (float*)d_out;

    k_sel<<<1, 32>>>(qr, rnd);                   // ~1us
    k_rstats<<<BFn, 256>>>(inp);                 // ~6us
    k_mem_mp<<<2 * Mn, 256>>>(mem1, mem2);       // ~100us (DRAM floor)
    k_gemm<<<dim3(16, KSPLIT), 256>>>();         // target ~30us (FMA floor)
    k_argmax<<<2 * BFn, 512>>>();                // ~4us
    k_out<<<OUTBLKS, 256>>>(inp, mem1, mem2, out, (long long)out_size);  // ~41us
}

// round 14
// speedup vs baseline: 1.1841x; 1.0734x over previous
#include <cuda_runtime.h>
#include <float.h>
#include <math.h>

// Problem constants
#define Bn   4
#define Qn   4
#define Fn   20
#define OBJn 20
#define Dn   4096
#define Mn   1000
#define ROWn (OBJn * Dn)          // 81920 floats per (frame|mem) row
#define BFn  (Bn * Fn)            // 80
#define KSPLIT 32
#define KPER   (Dn / KSPLIT)      // 128 k per block
#define MPAD 2048
#define OUTBLKS 1184

static const size_t RPN = (size_t)Qn * Bn * Fn * ROWn;   // 26,214,400 elems per big output

// ---------------- device scratch ----------------
__device__ float g_mem_mp[2 * Mn * Dn];          // 32.8 MB: normalized maxpooled mem rows
__device__ float g_rmaxn[BFn * Dn];              // normalized maxpooled R rows
__device__ float g_invnorm[BFn * OBJn];          // per-region inverse norms
__device__ float g_partial[KSPLIT * BFn * MPAD]; // 21 MB k-split partial dots
__device__ int   g_sim[2 * BFn];                 // sim1 (0..79), sim2 (80..159)
__device__ int   g_high[16], g_low[16];          // indexed by b*4+q

// ---------------- helpers ----------------
__device__ __forceinline__ float block_reduce_sum(float v) {
    __shared__ float sh[32];
    __shared__ float res;
    int lane = threadIdx.x & 31, w = threadIdx.x >> 5;
#pragma unroll
    for (int o = 16; o; o >>= 1) v += __shfl_down_sync(0xffffffffu, v, o);
    __syncthreads();
    if (!lane) sh[w] = v;
    __syncthreads();
    if (w == 0) {
        float x = (lane < (int)(blockDim.x >> 5)) ? sh[lane] : 0.f;
#pragma unroll
        for (int o = 16; o; o >>= 1) x += __shfl_down_sync(0xffffffffu, x, o);
        if (!lane) res = x;
    }
    __syncthreads();
    return res;
}

__device__ __forceinline__ float4 fmax4(float4 a, float4 b) {
    a.x = fmaxf(a.x, b.x); a.y = fmaxf(a.y, b.y);
    a.z = fmaxf(a.z, b.z); a.w = fmaxf(a.w, b.w);
    return a;
}

// ---------------- K_sel ----------------
__global__ void k_sel(const float* __restrict__ qr, const int* __restrict__ rnd) {
    int t = threadIdx.x;
    if (t >= 16) return;
    int b = t >> 2, q = t & 3;                // t = b*4 + q
    const float* w = qr + (b * Qn + q) * Fn;
    int hi = 0; float hv = w[0];
    for (int f = 1; f < Fn; f++) if (w[f] > hv) { hv = w[f]; hi = f; }
    int rr = rnd[b * Qn + q];
    int lo = 0;
    for (int i = 0; i < Fn; i++) {
        int rank = 0;
        for (int j = 0; j < Fn; j++)
            rank += (w[j] < w[i]) || (w[j] == w[i] && j < i);
        if (rank == rr) { lo = i; break; }
    }
    g_high[t] = hi; g_low[t] = lo;
}

// ---------------- K_rstats ----------------
__global__ __launch_bounds__(256) void k_rstats(const float* __restrict__ inp) {
    int bf = blockIdx.x;
    const float* base = inp + (size_t)bf * ROWn;
    float4 mx[4];
#pragma unroll
    for (int i = 0; i < 4; i++) mx[i] = make_float4(-FLT_MAX, -FLT_MAX, -FLT_MAX, -FLT_MAX);
    for (int o = 0; o < OBJn; o++) {
        float4 x[4];
        const float4* p = (const float4*)(base + (size_t)o * Dn);
        float s = 0.f;
#pragma unroll
        for (int i = 0; i < 4; i++) {
            x[i] = p[threadIdx.x + i * 256];
            s += x[i].x * x[i].x + x[i].y * x[i].y + x[i].z * x[i].z + x[i].w * x[i].w;
        }
        s = block_reduce_sum(s);
        float inv = 1.f / fmaxf(sqrtf(s), 1e-12f);
        if (threadIdx.x == 0) g_invnorm[bf * OBJn + o] = inv;
#pragma unroll
        for (int i = 0; i < 4; i++) {
            float4 v = x[i];
            v.x *= inv; v.y *= inv; v.z *= inv; v.w *= inv;
            mx[i] = fmax4(mx[i], v);
        }
    }
    float s2 = 0.f;
#pragma unroll
    for (int i = 0; i < 4; i++)
        s2 += mx[i].x * mx[i].x + mx[i].y * mx[i].y + mx[i].z * mx[i].z + mx[i].w * mx[i].w;
    s2 = block_reduce_sum(s2);
    float inv2 = 1.f / fmaxf(sqrtf(s2), 1e-12f);
    float4* out = (float4*)(g_rmaxn + (size_t)bf * Dn);
#pragma unroll
    for (int i = 0; i < 4; i++) {
        float4 v = mx[i];
        v.x *= inv2; v.y *= inv2; v.z *= inv2; v.w *= inv2;
        out[threadIdx.x + i * 256] = v;
    }
}

// ---------------- K_mem_mp (proven at DRAM floor) ----------------
__global__ __launch_bounds__(256) void k_mem_mp(const float* __restrict__ mem1,
                                                const float* __restrict__ mem2) {
    int row = blockIdx.x;
    const float* src = (row >= Mn) ? (mem2 + (size_t)(row - Mn) * ROWn)
                                   : (mem1 + (size_t)row * ROWn);
    float4 mx[4];
#pragma unroll
    for (int i = 0; i < 4; i++) mx[i] = make_float4(-FLT_MAX, -FLT_MAX, -FLT_MAX, -FLT_MAX);
    for (int o = 0; o < OBJn; o++) {
        const float4* p = (const float4*)(src + (size_t)o * Dn);
#pragma unroll
        for (int i = 0; i < 4; i++) mx[i] = fmax4(mx[i], p[threadIdx.x + i * 256]);
    }
    float s = 0.f;
#pragma unroll
    for (int i = 0; i < 4; i++)
        s += mx[i].x * mx[i].x + mx[i].y * mx[i].y + mx[i].z * mx[i].z + mx[i].w * mx[i].w;
    s = block_reduce_sum(s);
    float inv = 1.f / fmaxf(sqrtf(s), 1e-12f);
    float4* out = (float4*)(g_mem_mp + (size_t)row * Dn);
#pragma unroll
    for (int i = 0; i < 4; i++) {
        float4 v = mx[i];
        v.x *= inv; v.y *= inv; v.z *= inv; v.w *= inv;
        out[threadIdx.x + i * 256] = v;
    }
}

// ---------------- K_gemm v3: v2 layout + occupancy fix -------------------------------
// grid (16 m-tiles of 128, 32 k-splits of 128), 256 threads, reg-capped for 4 blocks/SM.
__global__ __launch_bounds__(256, 4) void k_gemm() {
    __shared__ float As[32][81];    // [kk][r]
    __shared__ float Bs[32][129];   // [kk][m]
    int tid = threadIdx.x;
    int tx = tid & 15;              // m group: 8 each -> 128
    int ty = tid >> 4;              // r group: 5 each -> 80
    int m0 = blockIdx.x * 128;
    int kbase = blockIdx.y * KPER;

    float acc[5][8];
#pragma unroll
    for (int i = 0; i < 5; i++)
#pragma unroll
        for (int j = 0; j < 8; j++) acc[i][j] = 0.f;

    for (int kc = 0; kc < KPER / 32; kc++) {
        int k0 = kbase + kc * 32;
        __syncthreads();
        // A tile: 80 r x 32 k, transposed store (conflict-free: bank=(4c4+17j+r)%32)
        for (int idx = tid; idx < 640; idx += 256) {
            int r = idx >> 3, c4 = idx & 7;
            float4 v = *(const float4*)(g_rmaxn + (size_t)r * Dn + k0 + c4 * 4);
            As[c4 * 4 + 0][r] = v.x; As[c4 * 4 + 1][r] = v.y;
            As[c4 * 4 + 2][r] = v.z; As[c4 * 4 + 3][r] = v.w;
        }
        // B tile: 128 m x 32 k, transposed store (conflict-free: bank=(4c4+j+m)%32)
#pragma unroll
        for (int l = 0; l < 4; l++) {
            int idx = tid + l * 256;
            int m = idx >> 3, c4 = idx & 7;
            int mg = m0 + m;
            float4 v = make_float4(0.f, 0.f, 0.f, 0.f);
            if (mg < 2 * Mn)
                v = *(const float4*)(g_mem_mp + (size_t)mg * Dn + k0 + c4 * 4);
            Bs[c4 * 4 + 0][m] = v.x; Bs[c4 * 4 + 1][m] = v.y;
            Bs[c4 * 4 + 2][m] = v.z; Bs[c4 * 4 + 3][m] = v.w;
        }
        __syncthreads();
#pragma unroll
        for (int kk = 0; kk < 32; kk++) {
            float a[5], b[8];
#pragma unroll
            for (int i = 0; i < 5; i++) a[i] = As[kk][ty * 5 + i];
#pragma unroll
            for (int j = 0; j < 8; j++) b[j] = Bs[kk][tx * 8 + j];
#pragma unroll
            for (int i = 0; i < 5; i++)
#pragma unroll
                for (int j = 0; j < 8; j++) acc[i][j] = fmaf(a[i], b[j], acc[i][j]);
        }
    }
    // vectorized partial store
    float* dst = g_partial + (size_t)blockIdx.y * BFn * MPAD;
#pragma unroll
    for (int i = 0; i < 5; i++) {
        float4* p = (float4*)(dst + (ty * 5 + i) * MPAD + m0 + tx * 8);
        p[0] = make_float4(acc[i][0], acc[i][1], acc[i][2], acc[i][3]);
        p[1] = make_float4(acc[i][4], acc[i][5], acc[i][6], acc[i][7]);
    }
}

// ---------------- K_argmax: one block per (row, mem-half) ----------------
__global__ __launch_bounds__(512) void k_argmax() {
    int r = blockIdx.x >> 1;
    int h = blockIdx.x & 1;
    int tid = threadIdx.x;
    float bv = -FLT_MAX;
    int   bm = 0;
    for (int m = tid; m < Mn; m += 512) {
        int mg = h * Mn + m;
        float s = 0.f;
#pragma unroll
        for (int ks = 0; ks < KSPLIT; ks++)
            s += g_partial[(size_t)ks * BFn * MPAD + (size_t)r * MPAD + mg];
        if (s > bv || (s == bv && m < bm)) { bv = s; bm = m; }
    }
    __shared__ float sv[512];
    __shared__ int   sm2[512];
    sv[tid] = bv; sm2[tid] = bm;
    __syncthreads();
    for (int st = 256; st; st >>= 1) {
        if (tid < st) {
            float ov = sv[tid + st]; int om = sm2[tid + st];
            if (ov > sv[tid] || (ov == sv[tid] && om < sm2[tid])) {
                sv[tid] = ov; sm2[tid] = om;
            }
        }
        __syncthreads();
    }
    if (tid == 0) g_sim[h * BFn + r] = sm2[0];
}

// ---------------- K_out: all output writes (R10-proven 41us) ----------------
#define FILL_ITEMS (BFn * 80)                 // 6400
#define REPL_ITEMS (32 * 16)                  // 512
#define NITEMS     (FILL_ITEMS + REPL_ITEMS + 1)

__global__ __launch_bounds__(256) void k_out(const float* __restrict__ inp,
                                             const float* __restrict__ mem1,
                                             const float* __restrict__ mem2,
                                             float* __restrict__ out,
                                             long long out_size) {
    int tid = threadIdx.x;
    float4* o4 = (float4*)out;
    const size_t rpn4 = RPN / 4;
    for (int it = blockIdx.x; it < NITEMS; it += gridDim.x) {
        if (it < FILL_ITEMS) {
            int bf = it / 80;
            int ch = it % 80;
            int b = bf / Fn, f = bf % Fn;
            int e4 = ch * 256 + tid;
            int oo = e4 >> 10;
            float inv = g_invnorm[bf * OBJn + oo];
            float4 v = ((const float4*)(inp + (size_t)bf * ROWn))[e4];
            v.x *= inv; v.y *= inv; v.z *= inv; v.w *= inv;
#pragma unroll
            for (int q = 0; q < 4; q++) {
                int lo = g_low[b * 4 + q], hi = g_high[b * 4 + q];
                size_t ob = ((size_t)((q * Bn + b) * Fn + f)) * (ROWn / 4) + e4;
                if (f != lo) o4[ob] = v;            // Rp copy
                if (f != hi) o4[rpn4 + ob] = v;     // Rn copy
            }
        } else if (it < FILL_ITEMS + REPL_ITEMS) {
            int ri = it - FILL_ITEMS;
            int t2 = ri / 16;
            int ch = ri % 16;
            int which = t2 & 1;                // 0: Rp/low/mem1  1: Rn/high/mem2
            int bq = t2 >> 1;
            int b = bq >> 2, q = bq & 3;
            int lo = g_low[bq];
            int f, row;
            const float* src;
            if (which == 0) { f = lo;         row = g_sim[b * Fn + lo];       src = mem1; }
            else            { f = g_high[bq]; row = g_sim[BFn + b * Fn + lo]; src = mem2; }
            const float4* s4 = (const float4*)(src + (size_t)row * ROWn);
            float4* d4 = (float4*)(out + (size_t)which * RPN +
                                   ((size_t)((q * Bn + b) * Fn + f)) * ROWn);
            int base = ch * 1280;
#pragma unroll
            for (int i = 0; i < 5; i++) {
                int e4 = base + tid + i * 256;
                d4[e4] = s4[e4];
            }
        } else {
            if (tid < 16) {
                int bq = tid;
                int b = bq >> 2, q = bq & 3;
                long long rpn2 = (long long)(2 * RPN);
                if (out_size >= rpn2 + 32) {
                    out[(size_t)rpn2 + (q * Bn + b)]      =
                        (float)g_sim[BFn + b * Fn + g_high[bq]];   // high_sim
                    out[(size_t)rpn2 + 16 + (q * Bn + b)] =
                        (float)g_sim[b * Fn + g_low[bq]];          // low_sim
                }
            }
        }
    }
}

// ---------------- launch: strictly serial, deterministic ----------------
extern "C" void kernel_launch(void* const* d_in, const int* in_sizes, int n_in,
                              void* d_out, int out_size) {
    const float* qr   = (const float*)d_in[0];   // [4,4,20]
    const float* inp  = (const float*)d_in[1];   // [4,20,20,4096]
    const float* mem1 = (const float*)d_in[2];   // [1000,81920]
    const float* mem2 = (const float*)d_in[3];   // [1000,81920]
    const int*   rnd  = (const int*)d_in[4];     // [4,4,1]
    float* out = (float*)d_out;

    k_sel<<<1, 32>>>(qr, rnd);                   // ~1us
    k_rstats<<<BFn, 256>>>(inp);                 // ~6us
    k_mem_mp<<<2 * Mn, 256>>>(mem1, mem2);       // ~100us (DRAM floor)
    k_gemm<<<dim3(16, KSPLIT), 256>>>();         // 512 blocks, 4 blocks/SM target
    k_argmax<<<2 * BFn, 512>>>();                // ~5us
    k_out<<<OUTBLKS, 256>>>(inp, mem1, mem2, out, (long long)out_size);  // ~41us
}